// round 1
// baseline (speedup 1.0000x reference)
#include <cuda_runtime.h>

// Psi11t flow force: F = 2*t*c0 * ( s x (Fs*b + Fbs) )
//   Fs  = 4-neighbor sum of s (periodic)
//   b   = s . Fs
//   Fbs = 4-neighbor sum of (s*b)
// Lattice: B=32, S=3, X=512, Y=512 (y contiguous). Power-of-2 dims -> mask wrap.

#define TX 16            // tile rows (x)
#define TY 64            // tile cols (y, contiguous)
#define HX (TX + 4)      // s tile with halo 2
#define HY (TY + 4)
#define BXD (TX + 2)     // b tile with halo 1
#define BYD (TY + 2)
#define NTHREADS 256

__global__ __launch_bounds__(NTHREADS) void psi11t_kernel(
    const float* __restrict__ s,
    const float* __restrict__ t,
    const float* __restrict__ c0,
    float* __restrict__ out)
{
    __shared__ float sh[3][HX][HY];     // 3*20*68*4  = 16320 B
    __shared__ float shb[BXD][BYD];     // 18*66*4    =  4752 B

    const int bb  = blockIdx.z;
    const int x0  = blockIdx.y * TX;
    const int y0  = blockIdx.x * TY;
    const int tid = threadIdx.x;
    const long base = (long)bb * (3L << 18);   // bb*3*512*512

    // ---- Phase 1: load s tile with halo 2 (periodic wrap via &511) ----
    for (int idx = tid; idx < 3 * HX * HY; idx += NTHREADS) {
        int c   = idx / (HX * HY);
        int rem = idx - c * (HX * HY);
        int lx  = rem / HY;
        int ly  = rem - lx * HY;
        int gx  = (x0 - 2 + lx) & 511;
        int gy  = (y0 - 2 + ly) & 511;
        sh[c][lx][ly] = s[base + ((long)c << 18) + ((long)gx << 9) + gy];
    }
    __syncthreads();

    // ---- Phase 2: b = s . nbr4(s) on tile with halo 1 ----
    for (int idx = tid; idx < BXD * BYD; idx += NTHREADS) {
        int lx = idx / BYD;
        int ly = idx - lx * BYD;
        int sx = lx + 1, sy = ly + 1;
        float b = 0.0f;
        #pragma unroll
        for (int c = 0; c < 3; ++c) {
            float nb = sh[c][sx - 1][sy] + sh[c][sx + 1][sy]
                     + sh[c][sx][sy - 1] + sh[c][sx][sy + 1];
            b = fmaf(sh[c][sx][sy], nb, b);
        }
        shb[lx][ly] = b;
    }
    __syncthreads();

    const float coeff = 2.0f * t[0] * c0[0];

    // ---- Phase 3: F = coeff * (s x (Fs*b + Fbs)) ----
    for (int idx = tid; idx < TX * TY; idx += NTHREADS) {
        int ix = idx / TY;
        int iy = idx - ix * TY;
        int sx = ix + 2, sy = iy + 2;   // sh coords
        int bx = ix + 1, by = iy + 1;   // shb coords

        float bc  = shb[bx][by];
        float bxm = shb[bx - 1][by], bxp = shb[bx + 1][by];
        float bym = shb[bx][by - 1], byp = shb[bx][by + 1];

        float Fv[3], sc[3];
        #pragma unroll
        for (int c = 0; c < 3; ++c) {
            float sxm = sh[c][sx - 1][sy], sxp = sh[c][sx + 1][sy];
            float sym = sh[c][sx][sy - 1], syp = sh[c][sx][sy + 1];
            float Fs  = sxm + sxp + sym + syp;
            float Fbs = fmaf(sxm, bxm, fmaf(sxp, bxp, fmaf(sym, bym, syp * byp)));
            Fv[c] = fmaf(Fs, bc, Fbs);
            sc[c] = sh[c][sx][sy];
        }

        float F0 = sc[1] * Fv[2] - sc[2] * Fv[1];
        float F1 = sc[2] * Fv[0] - sc[0] * Fv[2];
        float F2 = sc[0] * Fv[1] - sc[1] * Fv[0];

        long o = base + (((long)(x0 + ix)) << 9) + (y0 + iy);
        out[o]              = coeff * F0;
        out[o + (1L << 18)] = coeff * F1;
        out[o + (2L << 18)] = coeff * F2;
    }
}

extern "C" void kernel_launch(void* const* d_in, const int* in_sizes, int n_in,
                              void* d_out, int out_size)
{
    const float* s  = (const float*)d_in[0];
    const float* t  = (const float*)d_in[1];
    const float* c0 = (const float*)d_in[2];
    float* out = (float*)d_out;

    dim3 grid(512 / TY, 512 / TX, 32);   // (8, 32, 32) = 8192 blocks
    psi11t_kernel<<<grid, NTHREADS>>>(s, t, c0, out);
}

// round 2
// speedup vs baseline: 1.1556x; 1.1556x over previous
#include <cuda_runtime.h>

// Psi11t flow force: F = 2*t*c0 * ( s x (Fs*b + Fbs) )
//   Fs  = 4-neighbor sum of s (periodic), b = s . Fs, Fbs = nbr4(s*b)
// Lattice: B=32, S=3, X=512, Y=512 (y contiguous). Vectorized float4 in y.

#define MASK 511
#define TX 8            // tile rows (x)
#define TY 128          // tile cols (y)
#define PITCH 136       // smem row pitch in floats (16B-aligned rows, center at col 4)
#define SHX 12          // s rows incl. halo 2
#define BHX 10          // b rows incl. halo 1
#define NTH 256

__global__ __launch_bounds__(NTH) void psi11t_kernel(
    const float* __restrict__ s,
    const float* __restrict__ t,
    const float* __restrict__ c0,
    float* __restrict__ out)
{
    __shared__ float sh[3][SHX][PITCH];   // 3*12*136*4 = 19584 B
    __shared__ float shb[BHX][PITCH];     // 10*136*4   =  5440 B

    const int bb  = blockIdx.z;
    const int x0  = blockIdx.y * TX;
    const int y0  = blockIdx.x * TY;
    const int tid = threadIdx.x;
    const long base = (long)bb * (3L << 18);

    // ---- Phase 1: load s tile (halo 2 in x, halo 2 in y) ----
    // interior: per comp, SHX rows x 32 float4 (y0..y0+127)
    #pragma unroll
    for (int c = 0; c < 3; ++c) {
        const float* sp = s + base + ((long)c << 18);
        for (int idx = tid; idx < SHX * 32; idx += NTH) {
            int lx = idx >> 5;
            int v  = idx & 31;
            int gx = (x0 - 2 + lx) & MASK;
            float4 val = *(const float4*)(sp + ((long)gx << 9) + y0 + 4 * v);
            *(float4*)&sh[c][lx][4 + 4 * v] = val;
        }
    }
    // y halo columns: cols {2,3} <- y0-2,y0-1 ; cols {132,133} <- y0+128,y0+129
    if (tid < 144) {
        int c = (tid >= 96) ? 2 : (tid >= 48 ? 1 : 0);
        int r = (tid >> 2) - c * 12;
        int w = tid & 3;
        int gx = (x0 - 2 + r) & MASK;
        int gy = (w < 2) ? ((y0 - 2 + w) & MASK) : ((y0 + 126 + w) & MASK);
        int col = (w < 2) ? (2 + w) : (130 + w);
        sh[c][r][col] = s[base + ((long)c << 18) + ((long)gx << 9) + gy];
    }
    __syncthreads();

    // ---- Phase 2: b = s . nbr4(s), rows bx 0..9 (x halo 1), y halo 1 ----
    for (int idx = tid; idx < BHX * 32; idx += NTH) {
        int bx = idx >> 5;
        int v  = idx & 31;
        int lx = bx + 1;
        int col = 4 + 4 * v;
        float4 bv = make_float4(0.f, 0.f, 0.f, 0.f);
        #pragma unroll
        for (int c = 0; c < 3; ++c) {
            float4 ce = *(const float4*)&sh[c][lx][col];
            float4 xm = *(const float4*)&sh[c][lx - 1][col];
            float4 xp = *(const float4*)&sh[c][lx + 1][col];
            float  m1 = sh[c][lx][col - 1];
            float  p4 = sh[c][lx][col + 4];
            bv.x = fmaf(ce.x, xm.x + xp.x + m1   + ce.y, bv.x);
            bv.y = fmaf(ce.y, xm.y + xp.y + ce.x + ce.z, bv.y);
            bv.z = fmaf(ce.z, xm.z + xp.z + ce.y + ce.w, bv.z);
            bv.w = fmaf(ce.w, xm.w + xp.w + ce.z + p4  , bv.w);
        }
        *(float4*)&shb[bx][col] = bv;
    }
    // scalar b halo at cols 3 and 132
    if (tid < 2 * BHX) {
        int bx = tid >> 1;
        int side = tid & 1;
        int lx = bx + 1;
        int col = side ? 132 : 3;
        float b = 0.f;
        #pragma unroll
        for (int c = 0; c < 3; ++c) {
            float nb = sh[c][lx - 1][col] + sh[c][lx + 1][col]
                     + sh[c][lx][col - 1] + sh[c][lx][col + 1];
            b = fmaf(sh[c][lx][col], nb, b);
        }
        shb[bx][col] = b;
    }
    __syncthreads();

    const float coeff = 2.0f * t[0] * c0[0];

    // ---- Phase 3: one float4 task per thread (8 rows x 32 vec = 256) ----
    {
        int ix = tid >> 5;
        int v  = tid & 31;
        int lx = ix + 2;     // s row
        int bx = ix + 1;     // b row
        int col = 4 + 4 * v;

        float4 bc  = *(const float4*)&shb[bx][col];
        float4 bxm = *(const float4*)&shb[bx - 1][col];
        float4 bxp = *(const float4*)&shb[bx + 1][col];
        float  bm1 = shb[bx][col - 1];
        float  bp4 = shb[bx][col + 4];
        float4 bym = make_float4(bm1, bc.x, bc.y, bc.z);
        float4 byp = make_float4(bc.y, bc.z, bc.w, bp4);

        float4 Fv[3], sc[3];
        #pragma unroll
        for (int c = 0; c < 3; ++c) {
            float4 ce = *(const float4*)&sh[c][lx][col];
            float4 xm = *(const float4*)&sh[c][lx - 1][col];
            float4 xp = *(const float4*)&sh[c][lx + 1][col];
            float  m1 = sh[c][lx][col - 1];
            float  p4 = sh[c][lx][col + 4];
            float4 ym = make_float4(m1, ce.x, ce.y, ce.z);
            float4 yp = make_float4(ce.y, ce.z, ce.w, p4);

            float4 r;
            r.x = fmaf(xm.x + xp.x + ym.x + yp.x, bc.x,
                  fmaf(xm.x, bxm.x, fmaf(xp.x, bxp.x, fmaf(ym.x, bym.x, yp.x * byp.x))));
            r.y = fmaf(xm.y + xp.y + ym.y + yp.y, bc.y,
                  fmaf(xm.y, bxm.y, fmaf(xp.y, bxp.y, fmaf(ym.y, bym.y, yp.y * byp.y))));
            r.z = fmaf(xm.z + xp.z + ym.z + yp.z, bc.z,
                  fmaf(xm.z, bxm.z, fmaf(xp.z, bxp.z, fmaf(ym.z, bym.z, yp.z * byp.z))));
            r.w = fmaf(xm.w + xp.w + ym.w + yp.w, bc.w,
                  fmaf(xm.w, bxm.w, fmaf(xp.w, bxp.w, fmaf(ym.w, bym.w, yp.w * byp.w))));
            Fv[c] = r;
            sc[c] = ce;
        }

        float4 F0, F1, F2;
        F0.x = coeff * (sc[1].x * Fv[2].x - sc[2].x * Fv[1].x);
        F0.y = coeff * (sc[1].y * Fv[2].y - sc[2].y * Fv[1].y);
        F0.z = coeff * (sc[1].z * Fv[2].z - sc[2].z * Fv[1].z);
        F0.w = coeff * (sc[1].w * Fv[2].w - sc[2].w * Fv[1].w);
        F1.x = coeff * (sc[2].x * Fv[0].x - sc[0].x * Fv[2].x);
        F1.y = coeff * (sc[2].y * Fv[0].y - sc[0].y * Fv[2].y);
        F1.z = coeff * (sc[2].z * Fv[0].z - sc[0].z * Fv[2].z);
        F1.w = coeff * (sc[2].w * Fv[0].w - sc[0].w * Fv[2].w);
        F2.x = coeff * (sc[0].x * Fv[1].x - sc[1].x * Fv[0].x);
        F2.y = coeff * (sc[0].y * Fv[1].y - sc[1].y * Fv[0].y);
        F2.z = coeff * (sc[0].z * Fv[1].z - sc[1].z * Fv[0].z);
        F2.w = coeff * (sc[0].w * Fv[1].w - sc[1].w * Fv[0].w);

        long o = base + (((long)(x0 + ix)) << 9) + (y0 + 4 * v);
        *(float4*)(out + o)              = F0;
        *(float4*)(out + o + (1L << 18)) = F1;
        *(float4*)(out + o + (2L << 18)) = F2;
    }
}

extern "C" void kernel_launch(void* const* d_in, const int* in_sizes, int n_in,
                              void* d_out, int out_size)
{
    const float* s  = (const float*)d_in[0];
    const float* t  = (const float*)d_in[1];
    const float* c0 = (const float*)d_in[2];
    float* out = (float*)d_out;

    dim3 grid(512 / TY, 512 / TX, 32);   // (4, 64, 32) = 8192 blocks
    psi11t_kernel<<<grid, NTH>>>(s, t, c0, out);
}

// round 3
// speedup vs baseline: 1.8793x; 1.6262x over previous
#include <cuda_runtime.h>

// Psi11t flow force: F = 2*t*c0 * ( s x (Fs*b + Fbs) )
//   Fs = nbr4(s), b = s.Fs, Fbs = nbr4(s*b). Periodic 512x512, B=32, S=3.
// Register-marching stencil: 128 threads own the full Y=512 ring (float4 each),
// march 32 x-rows. y-boundary scalars exchanged via tiny double-buffered smem.

#define MASK 511
#define XCHUNK 32
#define NTH 128

__device__ __forceinline__ float4 operator+(float4 a, float4 b) {
    return make_float4(a.x + b.x, a.y + b.y, a.z + b.z, a.w + b.w);
}
__device__ __forceinline__ float4 operator*(float4 a, float4 b) {
    return make_float4(a.x * b.x, a.y * b.y, a.z * b.z, a.w * b.w);
}
__device__ __forceinline__ float4 fma4(float4 a, float4 b, float4 c) {
    return make_float4(fmaf(a.x, b.x, c.x), fmaf(a.y, b.y, c.y),
                       fmaf(a.z, b.z, c.z), fmaf(a.w, b.w, c.w));
}
// a*b - c*d, elementwise
__device__ __forceinline__ float4 crossm(float4 a, float4 b, float4 c, float4 d) {
    return make_float4(fmaf(a.x, b.x, -(c.x * d.x)), fmaf(a.y, b.y, -(c.y * d.y)),
                       fmaf(a.z, b.z, -(c.z * d.z)), fmaf(a.w, b.w, -(c.w * d.w)));
}
// shift down (y-1): {lw, a.x, a.y, a.z}
__device__ __forceinline__ float4 ymv(float4 a, float lw) {
    return make_float4(lw, a.x, a.y, a.z);
}
// shift up (y+1): {a.y, a.z, a.w, rx}
__device__ __forceinline__ float4 ypv(float4 a, float rx) {
    return make_float4(a.y, a.z, a.w, rx);
}
__device__ __forceinline__ float4 scale4(float k, float4 a) {
    return make_float4(k * a.x, k * a.y, k * a.z, k * a.w);
}

__global__ __launch_bounds__(NTH) void psi11t_kernel(
    const float* __restrict__ s,
    const float* __restrict__ tt,
    const float* __restrict__ c0,
    float* __restrict__ out)
{
    // boundary-exchange buffers: rows 0-2 = s comps, row 3 = b. Double buffered.
    __shared__ float wb[2][4][NTH];   // each thread's .w  (left value for t+1)
    __shared__ float xb[2][4][NTH];   // each thread's .x  (right value for t-1)

    const int bb = blockIdx.y;
    const int x0 = blockIdx.x * XCHUNK;
    const int t  = threadIdx.x;
    const int tm = (t - 1) & (NTH - 1);
    const int tp = (t + 1) & (NTH - 1);
    const long base = (long)bb * (3L << 18);
    const float* sb = s + base;
    const int yo = 4 * t;

    const float coeff = 2.0f * tt[0] * c0[0];

    float4 sP[3], sC[3], sN[3], sN2[3], sPF[3];
    float4 bP, bC, bN;
    float  sClw[3], sCrx[3], sNlw[3], sNrx[3];
    float  bClw, bCrx;

    // ---------------- Prologue: rows x0-2 .. x0+2 ----------------
    {
        float4 sA[3];
        #pragma unroll
        for (int c = 0; c < 3; ++c) {
            const float* cp = sb + ((long)c << 18) + yo;
            sA[c]  = *(const float4*)(cp + ((long)((x0 - 2) & MASK) << 9));
            sP[c]  = *(const float4*)(cp + ((long)((x0 - 1) & MASK) << 9));
            sC[c]  = *(const float4*)(cp + ((long)( x0      & MASK) << 9));
            sN[c]  = *(const float4*)(cp + ((long)((x0 + 1) & MASK) << 9));
            sN2[c] = *(const float4*)(cp + ((long)((x0 + 2) & MASK) << 9));
        }

        // sP bounds -> buf0
        #pragma unroll
        for (int c = 0; c < 3; ++c) { wb[0][c][t] = sP[c].w; xb[0][c][t] = sP[c].x; }
        __syncthreads();
        float plw[3], prx[3];
        #pragma unroll
        for (int c = 0; c < 3; ++c) { plw[c] = wb[0][c][tm]; prx[c] = xb[0][c][tp]; }

        // sC bounds -> buf1
        #pragma unroll
        for (int c = 0; c < 3; ++c) { wb[1][c][t] = sC[c].w; xb[1][c][t] = sC[c].x; }
        __syncthreads();
        #pragma unroll
        for (int c = 0; c < 3; ++c) { sClw[c] = wb[1][c][tm]; sCrx[c] = xb[1][c][tp]; }

        // bP = sP . (sA + sC + ym(sP) + yp(sP))
        bP = make_float4(0.f, 0.f, 0.f, 0.f);
        #pragma unroll
        for (int c = 0; c < 3; ++c)
            bP = fma4(sP[c], sA[c] + sC[c] + ymv(sP[c], plw[c]) + ypv(sP[c], prx[c]), bP);

        // bC = sC . (sP + sN + ym(sC) + yp(sC))
        bC = make_float4(0.f, 0.f, 0.f, 0.f);
        #pragma unroll
        for (int c = 0; c < 3; ++c)
            bC = fma4(sC[c], sP[c] + sN[c] + ymv(sC[c], sClw[c]) + ypv(sC[c], sCrx[c]), bC);

        // sN bounds + bC bounds -> buf0 (safe: buf0 readers done before last sync)
        #pragma unroll
        for (int c = 0; c < 3; ++c) { wb[0][c][t] = sN[c].w; xb[0][c][t] = sN[c].x; }
        wb[0][3][t] = bC.w; xb[0][3][t] = bC.x;
        __syncthreads();
        #pragma unroll
        for (int c = 0; c < 3; ++c) { sNlw[c] = wb[0][c][tm]; sNrx[c] = xb[0][c][tp]; }
        bClw = wb[0][3][tm]; bCrx = xb[0][3][tp];
    }

    // ---------------- Main loop: output rows x0 .. x0+31 ----------------
    #pragma unroll 1
    for (int i = 0; i < XCHUNK; ++i) {
        const int x = x0 + i;
        const int p = (i & 1) ^ 1;   // prologue used buf0 last; iter0 -> buf1

        // prefetch row x+3 (for next iteration's sN2)
        #pragma unroll
        for (int c = 0; c < 3; ++c)
            sPF[c] = *(const float4*)(sb + ((long)c << 18)
                                      + ((long)((x + 3) & MASK) << 9) + yo);

        // publish sN2 bounds
        #pragma unroll
        for (int c = 0; c < 3; ++c) { wb[p][c][t] = sN2[c].w; xb[p][c][t] = sN2[c].x; }

        // bN = sN . (sC + sN2 + ym(sN) + yp(sN))
        bN = make_float4(0.f, 0.f, 0.f, 0.f);
        #pragma unroll
        for (int c = 0; c < 3; ++c)
            bN = fma4(sN[c], sC[c] + sN2[c] + ymv(sN[c], sNlw[c]) + ypv(sN[c], sNrx[c]), bN);

        wb[p][3][t] = bN.w; xb[p][3][t] = bN.x;
        __syncthreads();

        float nlw[3], nrx[3];
        #pragma unroll
        for (int c = 0; c < 3; ++c) { nlw[c] = wb[p][c][tm]; nrx[c] = xb[p][c][tp]; }
        const float bNlw = wb[p][3][tm], bNrx = xb[p][3][tp];

        // F at row x
        const float4 bym = ymv(bC, bClw);
        const float4 byp = ypv(bC, bCrx);
        float4 Fv[3];
        #pragma unroll
        for (int c = 0; c < 3; ++c) {
            const float4 ymc = ymv(sC[c], sClw[c]);
            const float4 ypc = ypv(sC[c], sCrx[c]);
            const float4 Fs  = sP[c] + sN[c] + ymc + ypc;
            const float4 Fbs = fma4(sP[c], bP,
                               fma4(sN[c], bN,
                               fma4(ymc, bym, ypc * byp)));
            Fv[c] = fma4(Fs, bC, Fbs);
        }

        const float4 F0 = crossm(sC[1], Fv[2], sC[2], Fv[1]);
        const float4 F1 = crossm(sC[2], Fv[0], sC[0], Fv[2]);
        const float4 F2 = crossm(sC[0], Fv[1], sC[1], Fv[0]);

        float* op = out + base + (((long)x) << 9) + yo;
        *(float4*)(op)              = scale4(coeff, F0);
        *(float4*)(op + (1L << 18)) = scale4(coeff, F1);
        *(float4*)(op + (2L << 18)) = scale4(coeff, F2);

        // rotate pipeline
        #pragma unroll
        for (int c = 0; c < 3; ++c) {
            sP[c] = sC[c]; sC[c] = sN[c]; sN[c] = sN2[c]; sN2[c] = sPF[c];
            sClw[c] = sNlw[c]; sCrx[c] = sNrx[c];
            sNlw[c] = nlw[c];  sNrx[c] = nrx[c];
        }
        bP = bC; bC = bN;
        bClw = bNlw; bCrx = bNrx;
    }
}

extern "C" void kernel_launch(void* const* d_in, const int* in_sizes, int n_in,
                              void* d_out, int out_size)
{
    const float* s  = (const float*)d_in[0];
    const float* t  = (const float*)d_in[1];
    const float* c0 = (const float*)d_in[2];
    float* out = (float*)d_out;

    dim3 grid(512 / XCHUNK, 32);   // 16 x-strips * 32 batches = 512 blocks
    psi11t_kernel<<<grid, NTH>>>(s, t, c0, out);
}